// round 11
// baseline (speedup 1.0000x reference)
#include <cuda_runtime.h>
#include <math.h>

// MaskedNorm: B=8, T=4096, C=1024 fp32.
// k1 : dense read; masked rows -> partial sums, unmasked rows -> copy to out
// k2 : fold partials -> per-channel scale/shift
// k2b: compact masked-row indices (deterministic prefix scan, 1 block)
// k3 : normalize ONLY masked rows via dense compacted list

#define CCH   1024
#define C4    (CCH / 4)      // 256 float4 per row
#define RTOT  32768          // B*T
#define R4TOT (RTOT / 4)     // 8192 row-quads
#define NBLK  296            // k1 blocks: 2/SM x 148 SMs (1024 thr each)
#define G3    1184           // k3 blocks
#define EPSF  1e-4f

__device__ __align__(16) float g_psum[NBLK][CCH];
__device__ __align__(16) float g_psq [NBLK][CCH];
__device__ int   g_pcnt[NBLK];
__device__ __align__(16) float g_scale[CCH];
__device__ __align__(16) float g_shift[CCH];
__device__ int   g_rows[RTOT];   // compacted masked-row indices
__device__ int   g_nrows;        // count (rewritten every launch)

__device__ __forceinline__ void acc4(float4& s, float4& q, const float4 v) {
    s.x += v.x; s.y += v.y; s.z += v.z; s.w += v.w;
    q.x = fmaf(v.x, v.x, q.x);
    q.y = fmaf(v.y, v.y, q.y);
    q.z = fmaf(v.z, v.z, q.z);
    q.w = fmaf(v.w, v.w, q.w);
}

// ---------- k1: masked reduce + unmasked copy (dense streaming) ----------
__global__ __launch_bounds__(1024, 2)
void mn_main(const float4* __restrict__ y4, const int4* __restrict__ mask4,
             float4* __restrict__ out4) {
    __shared__ float4 ssum[4][256];
    __shared__ float4 ssq [4][256];
    __shared__ int    scnt[4];
    const int t = threadIdx.x & 255;   // channel slot (4 channels)
    const int g = threadIdx.x >> 8;    // row group 0..3
    const int p = blockIdx.x;

    float4 s = make_float4(0.f, 0.f, 0.f, 0.f);
    float4 q = make_float4(0.f, 0.f, 0.f, 0.f);
    int cnt = 0;

    for (int r4 = p * 4 + g; r4 < R4TOT; r4 += NBLK * 4) {
        const int  r  = r4 * 4;
        const int4 mk = __ldg(&mask4[r4]);
        if (mk.x > 0) { acc4(s, q, __ldg(&y4[(r + 0) * C4 + t])); cnt++; }
        else          { __stcs(&out4[(r + 0) * C4 + t], __ldcs(&y4[(r + 0) * C4 + t])); }
        if (mk.y > 0) { acc4(s, q, __ldg(&y4[(r + 1) * C4 + t])); cnt++; }
        else          { __stcs(&out4[(r + 1) * C4 + t], __ldcs(&y4[(r + 1) * C4 + t])); }
        if (mk.z > 0) { acc4(s, q, __ldg(&y4[(r + 2) * C4 + t])); cnt++; }
        else          { __stcs(&out4[(r + 2) * C4 + t], __ldcs(&y4[(r + 2) * C4 + t])); }
        if (mk.w > 0) { acc4(s, q, __ldg(&y4[(r + 3) * C4 + t])); cnt++; }
        else          { __stcs(&out4[(r + 3) * C4 + t], __ldcs(&y4[(r + 3) * C4 + t])); }
    }
    ssum[g][t] = s;
    ssq [g][t] = q;
    if (t == 0) scnt[g] = cnt;   // identical across t within a group
    __syncthreads();

    if (g == 0) {
        float4 S = ssum[0][t], Q = ssq[0][t];
        #pragma unroll
        for (int i = 1; i < 4; i++) {
            const float4 a = ssum[i][t], b = ssq[i][t];
            S.x += a.x; S.y += a.y; S.z += a.z; S.w += a.w;
            Q.x += b.x; Q.y += b.y; Q.z += b.z; Q.w += b.w;
        }
        reinterpret_cast<float4*>(g_psum[p])[t] = S;
        reinterpret_cast<float4*>(g_psq [p])[t] = Q;
        if (t == 0) g_pcnt[p] = scnt[0] + scnt[1] + scnt[2] + scnt[3];
    }
}

// ---------- k2: fold partials -> scale/shift (parallel, coalesced) ----------
__global__ __launch_bounds__(256, 8)
void mn_stats(const float* __restrict__ gamma, const float* __restrict__ beta) {
    __shared__ float ssum[8][32];
    __shared__ float ssq [8][32];
    __shared__ int   sn;
    const int lane = threadIdx.x & 31;
    const int w    = threadIdx.x >> 5;
    const int c    = blockIdx.x * 32 + lane;

    float s = 0.0f, q = 0.0f;
    #pragma unroll 4
    for (int p = w; p < NBLK; p += 8) {
        s += g_psum[p][c];
        q += g_psq [p][c];
    }
    ssum[w][lane] = s;
    ssq [w][lane] = q;

    if (w == 0) {
        int n = 0;
        for (int p = lane; p < NBLK; p += 32) n += g_pcnt[p];
        #pragma unroll
        for (int o = 16; o; o >>= 1) n += __shfl_down_sync(0xffffffffu, n, o);
        if (lane == 0) sn = n;
    }
    __syncthreads();

    if (w == 0) {
        float S = 0.0f, Q = 0.0f;
        #pragma unroll
        for (int i = 0; i < 8; i++) { S += ssum[i][lane]; Q += ssq[i][lane]; }
        const float nf   = (float)sn;
        const float mean = S / nf;
        const float var  = (Q - S * S / nf) / (nf - 1.0f);
        const float sd   = sqrtf(var);
        const float sc   = __ldg(&gamma[c]) / (sd + EPSF);
        g_scale[c] = sc;
        g_shift[c] = __ldg(&beta[c]) - mean * sc;   // out = fma(y, sc, shift)
    }
}

// ---------- k2b: compact masked-row indices (1 block, deterministic) ----------
// Thread tid owns rows [tid*32, (tid+1)*32). Local count -> block exclusive
// scan -> each thread writes its masked rows in ascending order.
__global__ __launch_bounds__(1024, 1)
void mn_compact(const int* __restrict__ mask) {
    __shared__ int warp_sum[32];
    const int tid  = threadIdx.x;
    const int lane = tid & 31;
    const int w    = tid >> 5;
    const int base = tid * 32;

    int m[32];
    int c = 0;
    #pragma unroll
    for (int i = 0; i < 32; i++) {
        m[i] = __ldg(&mask[base + i]);
        c += (m[i] > 0);
    }

    // exclusive scan of c over 1024 threads
    int x = c;
    #pragma unroll
    for (int o = 1; o < 32; o <<= 1) {
        const int v = __shfl_up_sync(0xffffffffu, x, o);
        if (lane >= o) x += v;
    }
    if (lane == 31) warp_sum[w] = x;      // inclusive warp total
    const int excl_in_warp = x - c;
    __syncthreads();
    if (w == 0) {
        int y = warp_sum[lane];
        #pragma unroll
        for (int o = 1; o < 32; o <<= 1) {
            const int v = __shfl_up_sync(0xffffffffu, y, o);
            if (lane >= o) y += v;
        }
        warp_sum[lane] = y - warp_sum[lane];   // exclusive warp offsets
        if (lane == 31) g_nrows = y;           // grand total (lane 31 has inclusive sum)
    }
    __syncthreads();

    int pos = warp_sum[w] + excl_in_warp;
    #pragma unroll
    for (int i = 0; i < 32; i++) {
        if (m[i] > 0) g_rows[pos++] = base + i;
    }
}

// ---------- k3: normalize masked rows via dense compacted list ----------
__global__ __launch_bounds__(256, 8)
void mn_norm(const float4* __restrict__ y4, float4* __restrict__ out4) {
    const int t = threadIdx.x;
    const float4 sc = reinterpret_cast<const float4*>(g_scale)[t];
    const float4 sh = reinterpret_cast<const float4*>(g_shift)[t];
    const int n = g_nrows;

    #pragma unroll 1
    for (int i = blockIdx.x; i < n; i += G3) {
        const int r = g_rows[i];
        float4 v = __ldg(&y4[r * C4 + t]);
        v.x = fmaf(v.x, sc.x, sh.x); v.y = fmaf(v.y, sc.y, sh.y);
        v.z = fmaf(v.z, sc.z, sh.z); v.w = fmaf(v.w, sc.w, sh.w);
        __stcs(&out4[r * C4 + t], v);
    }
}

extern "C" void kernel_launch(void* const* d_in, const int* in_sizes, int n_in,
                              void* d_out, int out_size) {
    const float* y     = (const float*)d_in[0];
    const int*   mask  = (const int*)  d_in[1];
    const float* gamma = (const float*)d_in[2];
    const float* beta  = (const float*)d_in[3];
    float*       out   = (float*)d_out;

    mn_main<<<NBLK, 1024>>>((const float4*)y, (const int4*)mask, (float4*)out);
    mn_compact<<<1, 1024>>>(mask);
    mn_stats<<<32, 256>>>(gamma, beta);
    mn_norm<<<G3, 256>>>((const float4*)y, (float4*)out);
}

// round 12
// speedup vs baseline: 1.2726x; 1.2726x over previous
#include <cuda_runtime.h>
#include <math.h>

// MaskedNorm: B=8, T=4096, C=1024 fp32.
// k1 : dense read; masked rows -> partial sums, unmasked rows -> copy to out
// kc : per-warp mask counts (ballot, coalesced)
// ks : replicated scan of warp counts + coalesced index scatter
// k2 : fold partials -> per-channel scale/shift
// k3 : normalize ONLY masked rows via dense compacted list

#define CCH   1024
#define C4    (CCH / 4)      // 256 float4 per row
#define RTOT  32768          // B*T
#define R4TOT (RTOT / 4)     // 8192 row-quads
#define NBLK  296            // k1 blocks: 2/SM x 148 SMs (1024 thr each)
#define NW    1024           // mask warps: 32768 / 32
#define G3    1184           // k3 blocks
#define EPSF  1e-4f

__device__ __align__(16) float g_psum[NBLK][CCH];
__device__ __align__(16) float g_psq [NBLK][CCH];
__device__ int   g_pcnt[NBLK];
__device__ __align__(16) float g_scale[CCH];
__device__ __align__(16) float g_shift[CCH];
__device__ int   g_wcnt[NW];     // per-warp masked counts
__device__ int   g_rows[RTOT];   // compacted masked-row indices
__device__ int   g_nrows;        // count (rewritten every launch)

__device__ __forceinline__ void acc4(float4& s, float4& q, const float4 v) {
    s.x += v.x; s.y += v.y; s.z += v.z; s.w += v.w;
    q.x = fmaf(v.x, v.x, q.x);
    q.y = fmaf(v.y, v.y, q.y);
    q.z = fmaf(v.z, v.z, q.z);
    q.w = fmaf(v.w, v.w, q.w);
}

// ---------- k1: masked reduce + unmasked copy (dense streaming) ----------
__global__ __launch_bounds__(1024, 2)
void mn_main(const float4* __restrict__ y4, const int4* __restrict__ mask4,
             float4* __restrict__ out4) {
    __shared__ float4 ssum[4][256];
    __shared__ float4 ssq [4][256];
    __shared__ int    scnt[4];
    const int t = threadIdx.x & 255;   // channel slot (4 channels)
    const int g = threadIdx.x >> 8;    // row group 0..3
    const int p = blockIdx.x;

    float4 s = make_float4(0.f, 0.f, 0.f, 0.f);
    float4 q = make_float4(0.f, 0.f, 0.f, 0.f);
    int cnt = 0;

    for (int r4 = p * 4 + g; r4 < R4TOT; r4 += NBLK * 4) {
        const int  r  = r4 * 4;
        const int4 mk = __ldg(&mask4[r4]);
        if (mk.x > 0) { acc4(s, q, __ldg(&y4[(r + 0) * C4 + t])); cnt++; }
        else          { __stcs(&out4[(r + 0) * C4 + t], __ldcs(&y4[(r + 0) * C4 + t])); }
        if (mk.y > 0) { acc4(s, q, __ldg(&y4[(r + 1) * C4 + t])); cnt++; }
        else          { __stcs(&out4[(r + 1) * C4 + t], __ldcs(&y4[(r + 1) * C4 + t])); }
        if (mk.z > 0) { acc4(s, q, __ldg(&y4[(r + 2) * C4 + t])); cnt++; }
        else          { __stcs(&out4[(r + 2) * C4 + t], __ldcs(&y4[(r + 2) * C4 + t])); }
        if (mk.w > 0) { acc4(s, q, __ldg(&y4[(r + 3) * C4 + t])); cnt++; }
        else          { __stcs(&out4[(r + 3) * C4 + t], __ldcs(&y4[(r + 3) * C4 + t])); }
    }
    ssum[g][t] = s;
    ssq [g][t] = q;
    if (t == 0) scnt[g] = cnt;
    __syncthreads();

    if (g == 0) {
        float4 S = ssum[0][t], Q = ssq[0][t];
        #pragma unroll
        for (int i = 1; i < 4; i++) {
            const float4 a = ssum[i][t], b = ssq[i][t];
            S.x += a.x; S.y += a.y; S.z += a.z; S.w += a.w;
            Q.x += b.x; Q.y += b.y; Q.z += b.z; Q.w += b.w;
        }
        reinterpret_cast<float4*>(g_psum[p])[t] = S;
        reinterpret_cast<float4*>(g_psq [p])[t] = Q;
        if (t == 0) g_pcnt[p] = scnt[0] + scnt[1] + scnt[2] + scnt[3];
    }
}

// ---------- kc: per-warp masked counts (coalesced ballot) ----------
__global__ __launch_bounds__(1024, 2)
void mn_count(const int* __restrict__ mask) {
    const int gw   = blockIdx.x * 32 + (threadIdx.x >> 5);  // global warp 0..1023
    const int lane = threadIdx.x & 31;
    const int m    = __ldg(&mask[gw * 32 + lane]);
    const unsigned b = __ballot_sync(0xffffffffu, m > 0);
    if (lane == 0) g_wcnt[gw] = __popc(b);
}

// ---------- ks: replicated exclusive scan + coalesced scatter ----------
// Every block loads all 1024 warp counts, computes the identical exclusive
// scan in smem (deterministic), then scatters indices for its own 32 warps.
__global__ __launch_bounds__(1024, 2)
void mn_scatter(const int* __restrict__ mask) {
    __shared__ int scnt[NW];     // exclusive offsets after scan
    __shared__ int wtot[32];
    const int tid  = threadIdx.x;
    const int lane = tid & 31;
    const int w    = tid >> 5;

    // load + intra-warp inclusive scan (each thread owns one count)
    int c = g_wcnt[tid];
    int x = c;
    #pragma unroll
    for (int o = 1; o < 32; o <<= 1) {
        const int v = __shfl_up_sync(0xffffffffu, x, o);
        if (lane >= o) x += v;
    }
    if (lane == 31) wtot[w] = x;
    __syncthreads();
    if (w == 0) {
        int y = wtot[lane];
        #pragma unroll
        for (int o = 1; o < 32; o <<= 1) {
            const int v = __shfl_up_sync(0xffffffffu, y, o);
            if (lane >= o) y += v;
        }
        if (lane == 31 && blockIdx.x == 0) g_nrows = y;   // grand total
        wtot[lane] = y - wtot[lane];                       // exclusive warp base
    }
    __syncthreads();
    scnt[tid] = wtot[w] + (x - c);     // exclusive offset for warp-count tid
    __syncthreads();

    // scatter: this block's 32 warps handle global warps gw
    const int gw = blockIdx.x * 32 + w;
    const int m  = __ldg(&mask[gw * 32 + lane]);
    const unsigned b = __ballot_sync(0xffffffffu, m > 0);
    if (m > 0) {
        const int rank = __popc(b & ((1u << lane) - 1u));
        g_rows[scnt[gw] + rank] = gw * 32 + lane;
    }
}

// ---------- k2: fold partials -> scale/shift (parallel, coalesced) ----------
__global__ __launch_bounds__(256, 8)
void mn_stats(const float* __restrict__ gamma, const float* __restrict__ beta) {
    __shared__ float ssum[8][32];
    __shared__ float ssq [8][32];
    __shared__ int   sn;
    const int lane = threadIdx.x & 31;
    const int w    = threadIdx.x >> 5;
    const int c    = blockIdx.x * 32 + lane;

    float s = 0.0f, q = 0.0f;
    #pragma unroll 4
    for (int p = w; p < NBLK; p += 8) {
        s += g_psum[p][c];
        q += g_psq [p][c];
    }
    ssum[w][lane] = s;
    ssq [w][lane] = q;

    if (w == 0) {
        int n = 0;
        for (int p = lane; p < NBLK; p += 32) n += g_pcnt[p];
        #pragma unroll
        for (int o = 16; o; o >>= 1) n += __shfl_down_sync(0xffffffffu, n, o);
        if (lane == 0) sn = n;
    }
    __syncthreads();

    if (w == 0) {
        float S = 0.0f, Q = 0.0f;
        #pragma unroll
        for (int i = 0; i < 8; i++) { S += ssum[i][lane]; Q += ssq[i][lane]; }
        const float nf   = (float)sn;
        const float mean = S / nf;
        const float var  = (Q - S * S / nf) / (nf - 1.0f);
        const float sd   = sqrtf(var);
        const float sc   = __ldg(&gamma[c]) / (sd + EPSF);
        g_scale[c] = sc;
        g_shift[c] = __ldg(&beta[c]) - mean * sc;   // out = fma(y, sc, shift)
    }
}

// ---------- k3: normalize masked rows via dense compacted list ----------
__global__ __launch_bounds__(256, 8)
void mn_norm(const float4* __restrict__ y4, float4* __restrict__ out4) {
    const int t = threadIdx.x;
    const float4 sc = reinterpret_cast<const float4*>(g_scale)[t];
    const float4 sh = reinterpret_cast<const float4*>(g_shift)[t];
    const int n = g_nrows;

    #pragma unroll 1
    for (int i = blockIdx.x; i < n; i += G3) {
        const int r = g_rows[i];
        float4 v = __ldg(&y4[r * C4 + t]);
        v.x = fmaf(v.x, sc.x, sh.x); v.y = fmaf(v.y, sc.y, sh.y);
        v.z = fmaf(v.z, sc.z, sh.z); v.w = fmaf(v.w, sc.w, sh.w);
        __stcs(&out4[r * C4 + t], v);
    }
}

extern "C" void kernel_launch(void* const* d_in, const int* in_sizes, int n_in,
                              void* d_out, int out_size) {
    const float* y     = (const float*)d_in[0];
    const int*   mask  = (const int*)  d_in[1];
    const float* gamma = (const float*)d_in[2];
    const float* beta  = (const float*)d_in[3];
    float*       out   = (float*)d_out;

    mn_main<<<NBLK, 1024>>>((const float4*)y, (const int4*)mask, (float4*)out);
    mn_count<<<32, 1024>>>(mask);
    mn_scatter<<<32, 1024>>>(mask);
    mn_stats<<<32, 256>>>(gamma, beta);
    mn_norm<<<G3, 256>>>((const float4*)y, (float4*)out);
}

// round 13
// speedup vs baseline: 1.3495x; 1.0605x over previous
#include <cuda_runtime.h>
#include <math.h>

// MaskedNorm: B=8, T=4096, C=1024 fp32.
// k1 : dense read; masked rows -> partial sums, unmasked rows -> copy to out
// kc : per-warp mask counts (ballot, coalesced)
// mid: blocks 0-31 fold partials->scale/shift; blocks 32-63 scan+scatter indices
// k3 : normalize ONLY masked rows via dense compacted list

#define CCH   1024
#define C4    (CCH / 4)      // 256 float4 per row
#define RTOT  32768          // B*T
#define R4TOT (RTOT / 4)     // 8192 row-quads
#define NBLK  296            // k1 blocks: 2/SM x 148 SMs (1024 thr each)
#define NW    1024           // mask warps: 32768 / 32
#define G3    1184           // k3 blocks
#define EPSF  1e-4f

__device__ __align__(16) float g_psum[NBLK][CCH];
__device__ __align__(16) float g_psq [NBLK][CCH];
__device__ int   g_pcnt[NBLK];
__device__ __align__(16) float g_scale[CCH];
__device__ __align__(16) float g_shift[CCH];
__device__ int   g_wcnt[NW];     // per-warp masked counts
__device__ int   g_rows[RTOT];   // compacted masked-row indices
__device__ int   g_nrows;        // count (rewritten every launch)

__device__ __forceinline__ void acc4(float4& s, float4& q, const float4 v) {
    s.x += v.x; s.y += v.y; s.z += v.z; s.w += v.w;
    q.x = fmaf(v.x, v.x, q.x);
    q.y = fmaf(v.y, v.y, q.y);
    q.z = fmaf(v.z, v.z, q.z);
    q.w = fmaf(v.w, v.w, q.w);
}

// ---------- k1: masked reduce + unmasked copy (dense streaming) ----------
__global__ __launch_bounds__(1024, 2)
void mn_main(const float4* __restrict__ y4, const int4* __restrict__ mask4,
             float4* __restrict__ out4) {
    __shared__ float4 ssum[4][256];
    __shared__ float4 ssq [4][256];
    __shared__ int    scnt[4];
    const int t = threadIdx.x & 255;   // channel slot (4 channels)
    const int g = threadIdx.x >> 8;    // row group 0..3
    const int p = blockIdx.x;

    float4 s = make_float4(0.f, 0.f, 0.f, 0.f);
    float4 q = make_float4(0.f, 0.f, 0.f, 0.f);
    int cnt = 0;

    for (int r4 = p * 4 + g; r4 < R4TOT; r4 += NBLK * 4) {
        const int  r  = r4 * 4;
        const int4 mk = __ldg(&mask4[r4]);
        if (mk.x > 0) { acc4(s, q, __ldg(&y4[(r + 0) * C4 + t])); cnt++; }
        else          { __stcs(&out4[(r + 0) * C4 + t], __ldcs(&y4[(r + 0) * C4 + t])); }
        if (mk.y > 0) { acc4(s, q, __ldg(&y4[(r + 1) * C4 + t])); cnt++; }
        else          { __stcs(&out4[(r + 1) * C4 + t], __ldcs(&y4[(r + 1) * C4 + t])); }
        if (mk.z > 0) { acc4(s, q, __ldg(&y4[(r + 2) * C4 + t])); cnt++; }
        else          { __stcs(&out4[(r + 2) * C4 + t], __ldcs(&y4[(r + 2) * C4 + t])); }
        if (mk.w > 0) { acc4(s, q, __ldg(&y4[(r + 3) * C4 + t])); cnt++; }
        else          { __stcs(&out4[(r + 3) * C4 + t], __ldcs(&y4[(r + 3) * C4 + t])); }
    }
    ssum[g][t] = s;
    ssq [g][t] = q;
    if (t == 0) scnt[g] = cnt;
    __syncthreads();

    if (g == 0) {
        float4 S = ssum[0][t], Q = ssq[0][t];
        #pragma unroll
        for (int i = 1; i < 4; i++) {
            const float4 a = ssum[i][t], b = ssq[i][t];
            S.x += a.x; S.y += a.y; S.z += a.z; S.w += a.w;
            Q.x += b.x; Q.y += b.y; Q.z += b.z; Q.w += b.w;
        }
        reinterpret_cast<float4*>(g_psum[p])[t] = S;
        reinterpret_cast<float4*>(g_psq [p])[t] = Q;
        if (t == 0) g_pcnt[p] = scnt[0] + scnt[1] + scnt[2] + scnt[3];
    }
}

// ---------- kc: per-warp masked counts (coalesced ballot) ----------
__global__ __launch_bounds__(1024, 2)
void mn_count(const int* __restrict__ mask) {
    const int gw   = blockIdx.x * 32 + (threadIdx.x >> 5);  // global warp 0..1023
    const int lane = threadIdx.x & 31;
    const int m    = __ldg(&mask[gw * 32 + lane]);
    const unsigned b = __ballot_sync(0xffffffffu, m > 0);
    if (lane == 0) g_wcnt[gw] = __popc(b);
}

// ---------- mid: blocks 0-31 stats fold; blocks 32-63 scan+scatter ----------
__global__ __launch_bounds__(1024, 2)
void mn_mid(const int* __restrict__ mask,
            const float* __restrict__ gamma, const float* __restrict__ beta) {
    __shared__ float sfs[32][33];    // stats: per-warp sums (padded)
    __shared__ float sfq[32][33];
    __shared__ int   sint[NW];       // scatter: exclusive offsets / stats: sn at [0]
    __shared__ int   wtot[32];

    const int tid  = threadIdx.x;
    const int lane = tid & 31;
    const int w    = tid >> 5;

    if (blockIdx.x < 32) {
        // ===== stats: 32 warps fold 296 partial slots for 32 channels =====
        const int c = blockIdx.x * 32 + lane;
        float s = 0.0f, q = 0.0f;
        for (int p = w; p < NBLK; p += 32) {   // ~9 rounds, coalesced 128B
            s += g_psum[p][c];
            q += g_psq [p][c];
        }
        sfs[w][lane] = s;
        sfq[w][lane] = q;

        if (w == 0) {
            int n = 0;
            for (int p = lane; p < NBLK; p += 32) n += g_pcnt[p];
            #pragma unroll
            for (int o = 16; o; o >>= 1) n += __shfl_down_sync(0xffffffffu, n, o);
            if (lane == 0) sint[0] = n;
        }
        __syncthreads();

        if (w == 0) {
            float S = 0.0f, Q = 0.0f;
            #pragma unroll
            for (int i = 0; i < 32; i++) { S += sfs[i][lane]; Q += sfq[i][lane]; }
            const float nf   = (float)sint[0];
            const float mean = S / nf;
            const float var  = (Q - S * S / nf) / (nf - 1.0f);
            const float sd   = sqrtf(var);
            const float sc   = __ldg(&gamma[c]) / (sd + EPSF);
            g_scale[c] = sc;
            g_shift[c] = __ldg(&beta[c]) - mean * sc;   // out = fma(y, sc, shift)
        }
    } else {
        // ===== scatter: replicated scan of g_wcnt + coalesced index writes =====
        const int sb = blockIdx.x - 32;
        int c = g_wcnt[tid];
        int x = c;
        #pragma unroll
        for (int o = 1; o < 32; o <<= 1) {
            const int v = __shfl_up_sync(0xffffffffu, x, o);
            if (lane >= o) x += v;
        }
        if (lane == 31) wtot[w] = x;
        __syncthreads();
        if (w == 0) {
            int y = wtot[lane];
            #pragma unroll
            for (int o = 1; o < 32; o <<= 1) {
                const int v = __shfl_up_sync(0xffffffffu, y, o);
                if (lane >= o) y += v;
            }
            if (lane == 31 && sb == 0) g_nrows = y;   // grand total
            wtot[lane] = y - wtot[lane];              // exclusive warp base
        }
        __syncthreads();
        sint[tid] = wtot[w] + (x - c);   // exclusive offset for warp-count tid
        __syncthreads();

        const int gw = sb * 32 + w;
        const int m  = __ldg(&mask[gw * 32 + lane]);
        const unsigned b = __ballot_sync(0xffffffffu, m > 0);
        if (m > 0) {
            const int rank = __popc(b & ((1u << lane) - 1u));
            g_rows[sint[gw] + rank] = gw * 32 + lane;
        }
    }
}

// ---------- k3: normalize masked rows via dense compacted list ----------
__global__ __launch_bounds__(256, 8)
void mn_norm(const float4* __restrict__ y4, float4* __restrict__ out4) {
    const int t = threadIdx.x;
    const float4 sc = reinterpret_cast<const float4*>(g_scale)[t];
    const float4 sh = reinterpret_cast<const float4*>(g_shift)[t];
    const int n = g_nrows;

    #pragma unroll 1
    for (int i = blockIdx.x; i < n; i += G3) {
        const int r = g_rows[i];
        float4 v = __ldg(&y4[r * C4 + t]);
        v.x = fmaf(v.x, sc.x, sh.x); v.y = fmaf(v.y, sc.y, sh.y);
        v.z = fmaf(v.z, sc.z, sh.z); v.w = fmaf(v.w, sc.w, sh.w);
        __stcs(&out4[r * C4 + t], v);
    }
}

extern "C" void kernel_launch(void* const* d_in, const int* in_sizes, int n_in,
                              void* d_out, int out_size) {
    const float* y     = (const float*)d_in[0];
    const int*   mask  = (const int*)  d_in[1];
    const float* gamma = (const float*)d_in[2];
    const float* beta  = (const float*)d_in[3];
    float*       out   = (float*)d_out;

    mn_main<<<NBLK, 1024>>>((const float4*)y, (const int4*)mask, (float4*)out);
    mn_count<<<32, 1024>>>(mask);
    mn_mid<<<64, 1024>>>(mask, gamma, beta);
    mn_norm<<<G3, 256>>>((const float4*)y, (float4*)out);
}

// round 14
// speedup vs baseline: 1.4218x; 1.0536x over previous
#include <cuda_runtime.h>
#include <math.h>

// MaskedNorm: B=8, T=4096, C=1024 fp32.
// k1: dense read; masked rows -> partial sums, unmasked rows -> copy to out
// k2: fold partials -> per-channel scale/shift (32 blocks x 1024 thr)
// k3: normalize masked rows only (unmasked already written by k1)

#define CCH   1024
#define C4    (CCH / 4)      // 256 float4 per row
#define RTOT  32768          // B*T
#define R4TOT (RTOT / 4)     // 8192 row-quads
#define R2TOT (RTOT / 2)     // 16384 row-pairs
#define NBLK  296            // k1 blocks: 2/SM x 148 SMs (1024 thr each)
#define G3    2048           // k3 blocks: 16384/2048 = 8 iters exact
#define EPSF  1e-4f

__device__ __align__(16) float g_psum[NBLK][CCH];
__device__ __align__(16) float g_psq [NBLK][CCH];
__device__ int   g_pcnt[NBLK];
__device__ __align__(16) float g_scale[CCH];
__device__ __align__(16) float g_shift[CCH];

__device__ __forceinline__ void acc4(float4& s, float4& q, const float4 v) {
    s.x += v.x; s.y += v.y; s.z += v.z; s.w += v.w;
    q.x = fmaf(v.x, v.x, q.x);
    q.y = fmaf(v.y, v.y, q.y);
    q.z = fmaf(v.z, v.z, q.z);
    q.w = fmaf(v.w, v.w, q.w);
}

// ---------- k1: masked reduce + unmasked copy (dense streaming) ----------
// 1024 threads = 4 row-groups x 256 channel-threads. Masked rows: __ldg
// (retained in L2 for k3). Unmasked rows: __ldcs + __stcs copy (evict-first).
__global__ __launch_bounds__(1024, 2)
void mn_main(const float4* __restrict__ y4, const int4* __restrict__ mask4,
             float4* __restrict__ out4) {
    __shared__ float4 ssum[4][256];
    __shared__ float4 ssq [4][256];
    __shared__ int    scnt[4];
    const int t = threadIdx.x & 255;   // channel slot (4 channels)
    const int g = threadIdx.x >> 8;    // row group 0..3
    const int p = blockIdx.x;

    float4 s = make_float4(0.f, 0.f, 0.f, 0.f);
    float4 q = make_float4(0.f, 0.f, 0.f, 0.f);
    int cnt = 0;

    for (int r4 = p * 4 + g; r4 < R4TOT; r4 += NBLK * 4) {
        const int  r  = r4 * 4;
        const int4 mk = __ldg(&mask4[r4]);
        if (mk.x > 0) { acc4(s, q, __ldg(&y4[(r + 0) * C4 + t])); cnt++; }
        else          { __stcs(&out4[(r + 0) * C4 + t], __ldcs(&y4[(r + 0) * C4 + t])); }
        if (mk.y > 0) { acc4(s, q, __ldg(&y4[(r + 1) * C4 + t])); cnt++; }
        else          { __stcs(&out4[(r + 1) * C4 + t], __ldcs(&y4[(r + 1) * C4 + t])); }
        if (mk.z > 0) { acc4(s, q, __ldg(&y4[(r + 2) * C4 + t])); cnt++; }
        else          { __stcs(&out4[(r + 2) * C4 + t], __ldcs(&y4[(r + 2) * C4 + t])); }
        if (mk.w > 0) { acc4(s, q, __ldg(&y4[(r + 3) * C4 + t])); cnt++; }
        else          { __stcs(&out4[(r + 3) * C4 + t], __ldcs(&y4[(r + 3) * C4 + t])); }
    }
    ssum[g][t] = s;
    ssq [g][t] = q;
    if (t == 0) scnt[g] = cnt;   // identical across t within a group
    __syncthreads();

    if (g == 0) {
        float4 S = ssum[0][t], Q = ssq[0][t];
        #pragma unroll
        for (int i = 1; i < 4; i++) {
            const float4 a = ssum[i][t], b = ssq[i][t];
            S.x += a.x; S.y += a.y; S.z += a.z; S.w += a.w;
            Q.x += b.x; Q.y += b.y; Q.z += b.z; Q.w += b.w;
        }
        reinterpret_cast<float4*>(g_psum[p])[t] = S;
        reinterpret_cast<float4*>(g_psq [p])[t] = Q;
        if (t == 0) g_pcnt[p] = scnt[0] + scnt[1] + scnt[2] + scnt[3];
    }
}

// ---------- k2: fold partials -> scale/shift (32 blocks x 1024 thr) ----------
// Block owns 32 channels; 32 warps stride over 296 partial slots (~9 coalesced
// 128B rounds each), then smem fold.
__global__ __launch_bounds__(1024, 2)
void mn_stats(const float* __restrict__ gamma, const float* __restrict__ beta) {
    __shared__ float sfs[32][33];
    __shared__ float sfq[32][33];
    __shared__ int   sn;
    const int lane = threadIdx.x & 31;
    const int w    = threadIdx.x >> 5;
    const int c    = blockIdx.x * 32 + lane;

    float s = 0.0f, q = 0.0f;
    for (int p = w; p < NBLK; p += 32) {
        s += g_psum[p][c];
        q += g_psq [p][c];
    }
    sfs[w][lane] = s;
    sfq[w][lane] = q;

    if (w == 0) {
        int n = 0;
        for (int p = lane; p < NBLK; p += 32) n += g_pcnt[p];
        #pragma unroll
        for (int o = 16; o; o >>= 1) n += __shfl_down_sync(0xffffffffu, n, o);
        if (lane == 0) sn = n;
    }
    __syncthreads();

    if (w == 0) {
        float S = 0.0f, Q = 0.0f;
        #pragma unroll
        for (int i = 0; i < 32; i++) { S += sfs[i][lane]; Q += sfq[i][lane]; }
        const float nf   = (float)sn;
        const float mean = S / nf;
        const float var  = (Q - S * S / nf) / (nf - 1.0f);
        const float sd   = sqrtf(var);
        const float sc   = __ldg(&gamma[c]) / (sd + EPSF);
        g_scale[c] = sc;
        g_shift[c] = __ldg(&beta[c]) - mean * sc;   // out = fma(y, sc, shift)
    }
}

// ---------- k3: normalize masked rows only (predicated; low MLP_p1) ----------
__global__ __launch_bounds__(256, 8)
void mn_norm(const float4* __restrict__ y4, const int* __restrict__ mask,
             float4* __restrict__ out4) {
    const int t = threadIdx.x;
    const float4 sc = reinterpret_cast<const float4*>(g_scale)[t];
    const float4 sh = reinterpret_cast<const float4*>(g_shift)[t];

    #pragma unroll 1
    for (int r2 = blockIdx.x; r2 < R2TOT; r2 += G3) {
        const int r  = r2 * 2;
        const int m0 = __ldg(&mask[r + 0]);
        const int m1 = __ldg(&mask[r + 1]);
        if (m0 > 0) {
            float4 v = __ldg(&y4[(r + 0) * C4 + t]);
            v.x = fmaf(v.x, sc.x, sh.x); v.y = fmaf(v.y, sc.y, sh.y);
            v.z = fmaf(v.z, sc.z, sh.z); v.w = fmaf(v.w, sc.w, sh.w);
            __stcs(&out4[(r + 0) * C4 + t], v);
        }
        if (m1 > 0) {
            float4 v = __ldg(&y4[(r + 1) * C4 + t]);
            v.x = fmaf(v.x, sc.x, sh.x); v.y = fmaf(v.y, sc.y, sh.y);
            v.z = fmaf(v.z, sc.z, sh.z); v.w = fmaf(v.w, sc.w, sh.w);
            __stcs(&out4[(r + 1) * C4 + t], v);
        }
    }
}

extern "C" void kernel_launch(void* const* d_in, const int* in_sizes, int n_in,
                              void* d_out, int out_size) {
    const float* y     = (const float*)d_in[0];
    const int*   mask  = (const int*)  d_in[1];
    const float* gamma = (const float*)d_in[2];
    const float* beta  = (const float*)d_in[3];
    float*       out   = (float*)d_out;

    mn_main<<<NBLK, 1024>>>((const float4*)y, (const int4*)mask, (float4*)out);
    mn_stats<<<32, 1024>>>(gamma, beta);
    mn_norm<<<G3, 256>>>((const float4*)y, mask, (float4*)out);
}